// round 2
// baseline (speedup 1.0000x reference)
#include <cuda_runtime.h>

#define MAXN 100000

// Scratch (static __device__ — no allocation allowed)
__device__ float  d_agg1[MAXN * 8];    // x (padded to 8) + sum of x[src], per dst
__device__ float  d_g[MAXN * 32];      // g = h_A @ w1b
__device__ float  d_agg2[MAXN * 32];   // sum of g[src], per dst
__device__ float2 d_sc[MAXN];          // (s0, s1) per node

__device__ __forceinline__ void red_add_v4(float* p, float a, float b, float c, float d) {
    asm volatile("red.global.add.v4.f32 [%0], {%1, %2, %3, %4};"
                 :: "l"(p), "f"(a), "f"(b), "f"(c), "f"(d) : "memory");
}

// K0: agg1 <- [x, 0pad], agg2 <- 0
__global__ void k0_init(const float* __restrict__ x, int N) {
    int n = blockIdx.x * blockDim.x + threadIdx.x;
    if (n >= N) return;
    const float* xr = x + (size_t)n * 7;
    float4* a1 = (float4*)(d_agg1 + n * 8);
    a1[0] = make_float4(xr[0], xr[1], xr[2], xr[3]);
    a1[1] = make_float4(xr[4], xr[5], xr[6], 0.f);
    float4 z = make_float4(0.f, 0.f, 0.f, 0.f);
    float4* a2 = (float4*)(d_agg2 + n * 32);
#pragma unroll
    for (int q = 0; q < 8; q++) a2[q] = z;
}

// K1: agg1[dst] += x[src]  (7 components; pad lane adds 0)
__global__ void k1_agg1(const int* __restrict__ ei, const float* __restrict__ x, int E) {
    int e = blockIdx.x * blockDim.x + threadIdx.x;
    if (e >= E) return;
    int s = __ldg(ei + e);
    int d = __ldg(ei + E + e);
    const float* xr = x + (size_t)s * 7;
    float x0 = __ldg(xr + 0), x1 = __ldg(xr + 1), x2 = __ldg(xr + 2), x3 = __ldg(xr + 3);
    float x4 = __ldg(xr + 4), x5 = __ldg(xr + 5), x6 = __ldg(xr + 6);
    float* ar = d_agg1 + d * 8;
    red_add_v4(ar,     x0, x1, x2, x3);
    red_add_v4(ar + 4, x4, x5, x6, 0.f);
}

// K2: per node: t[7] -> relu(t@w1a+b1a) -> (.)@w2a+b2a -> relu -> (.)@w1b = g[32]
__global__ void __launch_bounds__(128) k2_mlpA(
    const float* __restrict__ w1a, const float* __restrict__ b1a,
    const float* __restrict__ w2a, const float* __restrict__ b2a,
    const float* __restrict__ w1b, int N) {
    __shared__ float s_w1a[7 * 64];
    __shared__ float s_b1a[64];
    __shared__ float s_w2a[64 * 64];
    __shared__ float s_b2a[64];
    __shared__ float s_w1b[64 * 32];
    for (int i = threadIdx.x; i < 7 * 64; i += 128) s_w1a[i] = w1a[i];
    if (threadIdx.x < 64) { s_b1a[threadIdx.x] = b1a[threadIdx.x]; s_b2a[threadIdx.x] = b2a[threadIdx.x]; }
    for (int i = threadIdx.x; i < 64 * 64; i += 128) s_w2a[i] = w2a[i];
    for (int i = threadIdx.x; i < 64 * 32; i += 128) s_w1b[i] = w1b[i];
    __syncthreads();

    int n = blockIdx.x * 128 + threadIdx.x;
    if (n >= N) return;

    float t[7];
    const float* tr = d_agg1 + n * 8;
#pragma unroll
    for (int i = 0; i < 7; i++) t[i] = tr[i];

    float acc[64];
#pragma unroll
    for (int j = 0; j < 64; j++) acc[j] = 0.f;

#pragma unroll 1
    for (int k = 0; k < 64; k++) {
        float h = s_b1a[k];
#pragma unroll
        for (int i = 0; i < 7; i++) h = fmaf(t[i], s_w1a[i * 64 + k], h);
        h = fmaxf(h, 0.f);
#pragma unroll
        for (int j = 0; j < 64; j++) acc[j] = fmaf(h, s_w2a[k * 64 + j], acc[j]);
    }

    float g[32];
#pragma unroll
    for (int j = 0; j < 32; j++) g[j] = 0.f;
#pragma unroll 1
    for (int k = 0; k < 64; k++) {
        float h = fmaxf(acc[k] + s_b2a[k], 0.f);   // outer relu of layer A
#pragma unroll
        for (int j = 0; j < 32; j++) g[j] = fmaf(h, s_w1b[k * 32 + j], g[j]);
    }

    float4* gout = (float4*)(d_g + n * 32);
#pragma unroll
    for (int q = 0; q < 8; q++)
        gout[q] = make_float4(g[4 * q], g[4 * q + 1], g[4 * q + 2], g[4 * q + 3]);
}

// K3: agg2[dst] += g[src]  (32 components = 8 x red.v4) — dominant kernel
__global__ void k3_agg2(const int* __restrict__ ei, int E) {
    int e = blockIdx.x * blockDim.x + threadIdx.x;
    if (e >= E) return;
    int s = __ldg(ei + e);
    int d = __ldg(ei + E + e);
    const float4* gr = (const float4*)(d_g + s * 32);
    float* ar = d_agg2 + d * 32;
#pragma unroll
    for (int q = 0; q < 8; q++) {
        float4 v = __ldg(gr + q);
        red_add_v4(ar + 4 * q, v.x, v.y, v.z, v.w);
    }
}

// K4: per node: a = relu(g + agg2 + b1b); h2 = a@w2b + b2b; s0 = h2.ws[0:32], s1 = h2.ws[32:64]
__global__ void __launch_bounds__(128) k4_mlpB(
    const float* __restrict__ b1b, const float* __restrict__ w2b,
    const float* __restrict__ b2b, const float* __restrict__ ws, int N) {
    __shared__ float s_w2b[32 * 32];
    __shared__ float s_b1b[32];
    __shared__ float s_b2b[32];
    __shared__ float s_ws[64];
    for (int i = threadIdx.x; i < 32 * 32; i += 128) s_w2b[i] = w2b[i];
    if (threadIdx.x < 32) { s_b1b[threadIdx.x] = b1b[threadIdx.x]; s_b2b[threadIdx.x] = b2b[threadIdx.x]; }
    if (threadIdx.x < 64) s_ws[threadIdx.x] = ws[threadIdx.x];
    __syncthreads();

    int n = blockIdx.x * 128 + threadIdx.x;
    if (n >= N) return;

    const float* gr = d_g + n * 32;
    const float* ar = d_agg2 + n * 32;
    float acc[32];
#pragma unroll
    for (int j = 0; j < 32; j++) acc[j] = 0.f;
#pragma unroll 1
    for (int k = 0; k < 32; k++) {
        float a = fmaxf(gr[k] + ar[k] + s_b1b[k], 0.f);
#pragma unroll
        for (int j = 0; j < 32; j++) acc[j] = fmaf(a, s_w2b[k * 32 + j], acc[j]);
    }
    float s0 = 0.f, s1 = 0.f;
#pragma unroll
    for (int j = 0; j < 32; j++) {
        float h = acc[j] + s_b2b[j];
        s0 = fmaf(h, s_ws[j], s0);
        s1 = fmaf(h, s_ws[32 + j], s1);
    }
    d_sc[n] = make_float2(s0, s1);
}

// K5: out[i] = sigmoid(s0[c0] + s1[c1] + bs)
__global__ void k5_score(const int* __restrict__ cand, const float* __restrict__ bs,
                         float* __restrict__ out, int C) {
    int i = blockIdx.x * blockDim.x + threadIdx.x;
    if (i >= C) return;
    int2 ce = __ldg((const int2*)cand + i);
    float z = d_sc[ce.x].x + d_sc[ce.y].y + __ldg(bs);
    out[i] = 1.f / (1.f + __expf(-z));
}

extern "C" void kernel_launch(void* const* d_in, const int* in_sizes, int n_in,
                              void* d_out, int out_size) {
    const float* x    = (const float*)d_in[0];
    const int*   ei   = (const int*)d_in[1];
    const int*   cand = (const int*)d_in[2];
    const float* w1a = (const float*)d_in[3];
    const float* b1a = (const float*)d_in[4];
    const float* w2a = (const float*)d_in[5];
    const float* b2a = (const float*)d_in[6];
    const float* w1b = (const float*)d_in[7];
    const float* b1b = (const float*)d_in[8];
    const float* w2b = (const float*)d_in[9];
    const float* b2b = (const float*)d_in[10];
    const float* ws  = (const float*)d_in[11];
    const float* bs  = (const float*)d_in[12];

    int N = in_sizes[0] / 7;
    int E = in_sizes[1] / 2;
    int C = in_sizes[2] / 2;
    float* out = (float*)d_out;

    k0_init <<<(N + 255) / 256, 256>>>(x, N);
    k1_agg1 <<<(E + 255) / 256, 256>>>(ei, x, E);
    k2_mlpA <<<(N + 127) / 128, 128>>>(w1a, b1a, w2a, b2a, w1b, N);
    k3_agg2 <<<(E + 255) / 256, 256>>>(ei, E);
    k4_mlpB <<<(N + 127) / 128, 128>>>(b1b, w2b, b2b, ws, N);
    k5_score<<<(C + 255) / 256, 256>>>(cand, bs, out, C);
}

// round 3
// speedup vs baseline: 1.2366x; 1.2366x over previous
#include <cuda_runtime.h>

#define MAXN 100000
#define EMAX 6400000

// Static scratch (no allocation allowed)
__device__ float  d_x8[MAXN * 8];     // x padded to 8
__device__ float  d_agg1[MAXN * 8];   // x + sum x[src]
__device__ float  d_g[MAXN * 32];     // g = h_A @ w1b
__device__ int    d_deg[MAXN];
__device__ int    d_off[MAXN + 1];
__device__ int    d_cur[MAXN];
__device__ int    d_srcs[EMAX];       // CSR: sources grouped by dst
__device__ float2 d_sc[MAXN];         // (s0, s1) per node

// kA: pad x into d_x8, zero degree counters
__global__ void kA_init(const float* __restrict__ x, int N) {
    int n = blockIdx.x * blockDim.x + threadIdx.x;
    if (n >= N) return;
    const float* xr = x + (size_t)n * 7;
    float4* p = (float4*)(d_x8 + n * 8);
    p[0] = make_float4(xr[0], xr[1], xr[2], xr[3]);
    p[1] = make_float4(xr[4], xr[5], xr[6], 0.f);
    d_deg[n] = 0;
}

// kB: histogram of dst
__global__ void kB_hist(const int* __restrict__ ei, int E) {
    int e = blockIdx.x * blockDim.x + threadIdx.x;
    if (e >= E) return;
    atomicAdd(&d_deg[__ldg(ei + E + e)], 1);
}

// kC: exclusive scan over d_deg -> d_off, copy to d_cur. Single block.
__global__ void __launch_bounds__(1024) kC_scan(int N) {
    __shared__ int s_part[1024];
    int tid = threadIdx.x;
    int chunk = (N + 1023) >> 10;
    int b = tid * chunk;
    int e = min(b + chunk, N);
    int sum = 0;
    for (int i = b; i < e; i++) sum += d_deg[i];
    s_part[tid] = sum;
    __syncthreads();
    // inclusive Hillis-Steele scan
    for (int ofs = 1; ofs < 1024; ofs <<= 1) {
        int v = (tid >= ofs) ? s_part[tid - ofs] : 0;
        __syncthreads();
        s_part[tid] += v;
        __syncthreads();
    }
    int run = s_part[tid] - sum;   // exclusive start for this chunk
    for (int i = b; i < e; i++) {
        d_off[i] = run;
        d_cur[i] = run;
        run += d_deg[i];
    }
    if (tid == 1023) d_off[N] = s_part[1023];
}

// kD: scatter sources into dst buckets
__global__ void kD_scatter(const int* __restrict__ ei, int E) {
    int e = blockIdx.x * blockDim.x + threadIdx.x;
    if (e >= E) return;
    int s = __ldg(ei + e);
    int d = __ldg(ei + E + e);
    int pos = atomicAdd(&d_cur[d], 1);
    d_srcs[pos] = s;
}

// kE: agg1[n] = x8[n] + sum_{s in N(n)} x8[s].  8 lanes/node, 4 nodes/warp.
__global__ void kE_agg1(int N) {
    int t = blockIdx.x * blockDim.x + threadIdx.x;
    int lane = t & 31;
    int node = (t >> 5) * 4 + (lane >> 3);
    int j = lane & 7;
    if (node >= N) return;
    int b = d_off[node], en = d_off[node + 1];
    float acc = d_x8[node * 8 + j];
    for (int i = b; i < en; i++) {
        int s = __ldg(d_srcs + i);
        acc += __ldg(d_x8 + s * 8 + j);
    }
    d_agg1[node * 8 + j] = acc;
}

// k2: per node: t[7] -> relu(t@w1a+b1a) -> @w2a+b2a -> relu -> @w1b = g[32]
__global__ void __launch_bounds__(128) k2_mlpA(
    const float* __restrict__ w1a, const float* __restrict__ b1a,
    const float* __restrict__ w2a, const float* __restrict__ b2a,
    const float* __restrict__ w1b, int N) {
    __shared__ float s_w1a[7 * 64];
    __shared__ float s_b1a[64];
    __shared__ float s_w2a[64 * 64];
    __shared__ float s_b2a[64];
    __shared__ float s_w1b[64 * 32];
    for (int i = threadIdx.x; i < 7 * 64; i += 128) s_w1a[i] = w1a[i];
    if (threadIdx.x < 64) { s_b1a[threadIdx.x] = b1a[threadIdx.x]; s_b2a[threadIdx.x] = b2a[threadIdx.x]; }
    for (int i = threadIdx.x; i < 64 * 64; i += 128) s_w2a[i] = w2a[i];
    for (int i = threadIdx.x; i < 64 * 32; i += 128) s_w1b[i] = w1b[i];
    __syncthreads();

    int n = blockIdx.x * 128 + threadIdx.x;
    if (n >= N) return;

    float tin[7];
    const float* tr = d_agg1 + n * 8;
#pragma unroll
    for (int i = 0; i < 7; i++) tin[i] = tr[i];

    float acc[64];
#pragma unroll
    for (int j = 0; j < 64; j++) acc[j] = 0.f;
#pragma unroll 1
    for (int k = 0; k < 64; k++) {
        float h = s_b1a[k];
#pragma unroll
        for (int i = 0; i < 7; i++) h = fmaf(tin[i], s_w1a[i * 64 + k], h);
        h = fmaxf(h, 0.f);
#pragma unroll
        for (int j = 0; j < 64; j++) acc[j] = fmaf(h, s_w2a[k * 64 + j], acc[j]);
    }

    float g[32];
#pragma unroll
    for (int j = 0; j < 32; j++) g[j] = 0.f;
#pragma unroll 1
    for (int k = 0; k < 64; k++) {
        float h = fmaxf(acc[k] + s_b2a[k], 0.f);   // outer relu of layer A
#pragma unroll
        for (int j = 0; j < 32; j++) g[j] = fmaf(h, s_w1b[k * 32 + j], g[j]);
    }

    float4* gout = (float4*)(d_g + n * 32);
#pragma unroll
    for (int q = 0; q < 8; q++)
        gout[q] = make_float4(g[4 * q], g[4 * q + 1], g[4 * q + 2], g[4 * q + 3]);
}

// kF: warp per node: agg2 gather (coalesced) + mlpB + score scalars, fused.
__global__ void __launch_bounds__(256) kF_agg2_mlpB(
    const float* __restrict__ b1b, const float* __restrict__ w2b,
    const float* __restrict__ b2b, const float* __restrict__ ws, int N) {
    __shared__ float s_w2b[32 * 32];
    for (int i = threadIdx.x; i < 1024; i += 256) s_w2b[i] = w2b[i];
    __syncthreads();

    int lane = threadIdx.x & 31;
    int node = blockIdx.x * 8 + (threadIdx.x >> 5);
    if (node >= N) return;

    int b = d_off[node], en = d_off[node + 1];
    float acc = __ldg(d_g + node * 32 + lane);   // self term g[n]
    for (int i = b; i < en; i += 32) {
        int myid = (i + lane < en) ? __ldg(d_srcs + i + lane) : 0;
        int m = min(32, en - i);
        for (int k = 0; k < m; k++) {
            int s = __shfl_sync(0xffffffffu, myid, k);
            acc += __ldg(d_g + s * 32 + lane);   // 128B coalesced per src row
        }
    }
    float a = fmaxf(acc + __ldg(b1b + lane), 0.f);

    // h2 = a @ w2b + b2b via shfl broadcast
    float h2 = __ldg(b2b + lane);
#pragma unroll
    for (int k = 0; k < 32; k++) {
        float ak = __shfl_sync(0xffffffffu, a, k);
        h2 = fmaf(ak, s_w2b[k * 32 + lane], h2);
    }
    float s0 = h2 * __ldg(ws + lane);
    float s1 = h2 * __ldg(ws + 32 + lane);
#pragma unroll
    for (int o = 16; o > 0; o >>= 1) {
        s0 += __shfl_down_sync(0xffffffffu, s0, o);
        s1 += __shfl_down_sync(0xffffffffu, s1, o);
    }
    if (lane == 0) d_sc[node] = make_float2(s0, s1);
}

// k5: out[i] = sigmoid(s0[c0] + s1[c1] + bs)
__global__ void k5_score(const int* __restrict__ cand, const float* __restrict__ bs,
                         float* __restrict__ out, int C) {
    int i = blockIdx.x * blockDim.x + threadIdx.x;
    if (i >= C) return;
    int2 ce = __ldg((const int2*)cand + i);
    float z = d_sc[ce.x].x + d_sc[ce.y].y + __ldg(bs);
    out[i] = 1.f / (1.f + __expf(-z));
}

extern "C" void kernel_launch(void* const* d_in, const int* in_sizes, int n_in,
                              void* d_out, int out_size) {
    const float* x    = (const float*)d_in[0];
    const int*   ei   = (const int*)d_in[1];
    const int*   cand = (const int*)d_in[2];
    const float* w1a = (const float*)d_in[3];
    const float* b1a = (const float*)d_in[4];
    const float* w2a = (const float*)d_in[5];
    const float* b2a = (const float*)d_in[6];
    const float* w1b = (const float*)d_in[7];
    const float* b1b = (const float*)d_in[8];
    const float* w2b = (const float*)d_in[9];
    const float* b2b = (const float*)d_in[10];
    const float* ws  = (const float*)d_in[11];
    const float* bs  = (const float*)d_in[12];

    int N = in_sizes[0] / 7;
    int E = in_sizes[1] / 2;
    int C = in_sizes[2] / 2;
    float* out = (float*)d_out;

    kA_init   <<<(N + 255) / 256, 256>>>(x, N);
    kB_hist   <<<(E + 255) / 256, 256>>>(ei, E);
    kC_scan   <<<1, 1024>>>(N);
    kD_scatter<<<(E + 255) / 256, 256>>>(ei, E);
    kE_agg1   <<<(N + 31) / 32, 256>>>(N);
    k2_mlpA   <<<(N + 127) / 128, 128>>>(w1a, b1a, w2a, b2a, w1b, N);
    kF_agg2_mlpB<<<(N + 7) / 8, 256>>>(b1b, w2b, b2b, ws, N);
    k5_score  <<<(C + 255) / 256, 256>>>(cand, bs, out, C);
}